// round 15
// baseline (speedup 1.0000x reference)
#include <cuda_runtime.h>
#include <cstdint>

#define N_NODES 100000
#define N_EDGES 1250000
#define D 64
#define CAP 96                            // bucket capacity; P(deg>96)~1e-50; int4-aligned
#define ZBLKS ((N_NODES + 1023) / 1024)   // 98

// Scratch (static device globals — no allocation allowed)
__device__ __align__(128) float g_a1[(size_t)N_NODES * D];  // A1 = agg(x)
__device__ __align__(128) float g_a2[(size_t)N_NODES * D];  // A2 = agg(A1)
__device__ __align__(16) int g_slot[(size_t)N_NODES * CAP]; // bucketed src ids
__device__ int   g_cnt[N_NODES];                            // degree / cursor
__device__ float g_W2[D * D];                  // W @ W
__device__ float g_bW[D];                      // b @ W^T
__device__ int   g_is64;

// ---------------------------------------------------------------------------
// Fused init: blocks [0,98) zero g_cnt; [98,114) compute W2; 114: bW + detect.
// ---------------------------------------------------------------------------
__global__ void init2_kernel(const unsigned* __restrict__ ei,
                             const float* __restrict__ W,
                             const float* __restrict__ b) {
    int t = threadIdx.x;                 // 256
    int bid = blockIdx.x;
    if (bid < ZBLKS) {
        int i4 = bid * 1024 + t * 4;
        if (i4 < N_NODES)
            *reinterpret_cast<int4*>(&g_cnt[i4]) = make_int4(0, 0, 0, 0);
        return;
    }
    __shared__ float Wsh[D * D];
    #pragma unroll
    for (int i = t; i < D * D; i += 256) Wsh[i] = W[i];
    __syncthreads();
    if (bid < ZBLKS + 16) {
        int o = (bid - ZBLKS) * 256 + t;
        int j = o >> 6, k = o & 63;
        float s = 0.f;
        #pragma unroll
        for (int m = 0; m < D; m++) s += Wsh[j * D + m] * Wsh[m * D + k];
        g_W2[o] = s;
    } else {
        if (t < D) {
            float s = 0.f;
            #pragma unroll
            for (int k = 0; k < D; k++) s += b[k] * Wsh[t * D + k];
            g_bW[t] = s;
        } else if (t == 64) {
            int all0 = 1;
            #pragma unroll 1
            for (int k = 0; k < 64; k++) {
                if (ei[2 * k + 1] != 0u) { all0 = 0; break; }
            }
            g_is64 = all0;
        }
    }
}

// ---------------------------------------------------------------------------
// One-pass bucket fill: slot[dst*CAP + pos] = src. 8 edges/thread.
// ---------------------------------------------------------------------------
__global__ void bucket_kernel(const void* __restrict__ ei) {
    int q = blockIdx.x * blockDim.x + threadIdx.x;
    int e = q * 8;
    if (e >= N_EDGES) return;
    int s[8], d[8];
    if (g_is64) {
        const longlong2* ps = reinterpret_cast<const longlong2*>((const long long*)ei + e);
        const longlong2* pd = reinterpret_cast<const longlong2*>((const long long*)ei + N_EDGES + e);
        #pragma unroll
        for (int i = 0; i < 4; i++) {
            longlong2 a = __ldg(ps + i);
            longlong2 u = __ldg(pd + i);
            s[2 * i] = (int)a.x; s[2 * i + 1] = (int)a.y;
            d[2 * i] = (int)u.x; d[2 * i + 1] = (int)u.y;
        }
    } else {
        const int4* ps = reinterpret_cast<const int4*>((const int*)ei + e);
        const int4* pd = reinterpret_cast<const int4*>((const int*)ei + N_EDGES + e);
        #pragma unroll
        for (int i = 0; i < 2; i++) {
            int4 a = __ldg(ps + i);
            int4 u = __ldg(pd + i);
            s[4 * i] = a.x; s[4 * i + 1] = a.y; s[4 * i + 2] = a.z; s[4 * i + 3] = a.w;
            d[4 * i] = u.x; d[4 * i + 1] = u.y; d[4 * i + 2] = u.z; d[4 * i + 3] = u.w;
        }
    }
    int p[8];
    #pragma unroll
    for (int i = 0; i < 8; i++) p[i] = atomicAdd(&g_cnt[d[i]], 1);
    #pragma unroll
    for (int i = 0; i < 8; i++)
        if (p[i] < CAP) g_slot[(size_t)d[i] * CAP + p[i]] = s[i];
}

// ---------------------------------------------------------------------------
// Gather (fp32): phase 0: x -> g_a1, phase 1: g_a1 -> g_a2.
// 32 lanes per node: lanes 0-15 (half 0) process even int4-groups, lanes
// 16-31 (half 1) odd groups; same chunk c = lane&15. Final shfl_xor(16)
// combine. Halves the serial group chain per node, doubles warp parallelism.
// ---------------------------------------------------------------------------
__global__ void gather_kernel(const float* __restrict__ x, int phase) {
    int gt = blockIdx.x * blockDim.x + threadIdx.x;
    int node = gt >> 5;
    int lane = gt & 31;
    int c = lane & 15;
    int half = lane >> 4;
    if (node >= N_NODES) return;

    const float* in = phase ? g_a1 : x;
    float* outp     = phase ? g_a2 : g_a1;

    int cnt = __ldg(&g_cnt[node]);
    if (cnt > CAP) cnt = CAP;
    const int4* slots4 = reinterpret_cast<const int4*>(g_slot + (size_t)node * CAP);
    const int ngroups = (cnt + 3) >> 2;

    float4 acc = make_float4(0.f, 0.f, 0.f, 0.f);
    #pragma unroll 2
    for (int q = half; q < ngroups; q += 2) {
        int4 s = __ldg(&slots4[q]);
        int base = q * 4;
        if (base + 0 < cnt) {
            float4 v = *reinterpret_cast<const float4*>(in + (size_t)s.x * D + c * 4);
            acc.x += v.x; acc.y += v.y; acc.z += v.z; acc.w += v.w;
        }
        if (base + 1 < cnt) {
            float4 v = *reinterpret_cast<const float4*>(in + (size_t)s.y * D + c * 4);
            acc.x += v.x; acc.y += v.y; acc.z += v.z; acc.w += v.w;
        }
        if (base + 2 < cnt) {
            float4 v = *reinterpret_cast<const float4*>(in + (size_t)s.z * D + c * 4);
            acc.x += v.x; acc.y += v.y; acc.z += v.z; acc.w += v.w;
        }
        if (base + 3 < cnt) {
            float4 v = *reinterpret_cast<const float4*>(in + (size_t)s.w * D + c * 4);
            acc.x += v.x; acc.y += v.y; acc.z += v.z; acc.w += v.w;
        }
    }

    // combine the two halves (lane i <- lane i+16)
    acc.x += __shfl_xor_sync(0xffffffffu, acc.x, 16);
    acc.y += __shfl_xor_sync(0xffffffffu, acc.y, 16);
    acc.z += __shfl_xor_sync(0xffffffffu, acc.z, 16);
    acc.w += __shfl_xor_sync(0xffffffffu, acc.w, 16);

    if (half == 0)
        *reinterpret_cast<float4*>(outp + (size_t)node * D + c * 4) = acc;
}

// ---------------------------------------------------------------------------
// Dual GEMM per 64-row tile:
//   phase 1:  hid = A1 @ W^T  + b
//   phase 2:  out = A2 @ W2^T + deg*bW + b
// 4x4 register tile, fma.rn.f32x2 (FFMA2).
// ---------------------------------------------------------------------------
#define SROW 68

__device__ __forceinline__ void stage_a_tile(float* As, const float* __restrict__ src,
                                             int row0, int t) {
    #pragma unroll
    for (int i = t; i < 64 * 16; i += 256) {
        int r = i >> 4, k4 = i & 15;
        int row = row0 + r;
        float4 v = make_float4(0.f, 0.f, 0.f, 0.f);
        if (row < N_NODES)
            v = reinterpret_cast<const float4*>(src)[(size_t)row * 16 + k4];
        *reinterpret_cast<float4*>(&As[r * SROW + k4 * 4]) = v;
    }
}

__device__ __forceinline__ void gemm_tile(const float* As, const float* Ws,
                                          unsigned long long acc[4][4],
                                          int tx, int ty) {
    #pragma unroll 4
    for (int k4 = 0; k4 < 16; k4++) {
        ulonglong2 a[4], w[4];
        #pragma unroll
        for (int ri = 0; ri < 4; ri++)
            a[ri] = *reinterpret_cast<const ulonglong2*>(&As[(ty * 4 + ri) * SROW + k4 * 4]);
        #pragma unroll
        for (int ji = 0; ji < 4; ji++)
            w[ji] = *reinterpret_cast<const ulonglong2*>(&Ws[(tx + 16 * ji) * SROW + k4 * 4]);
        #pragma unroll
        for (int ri = 0; ri < 4; ri++)
            #pragma unroll
            for (int ji = 0; ji < 4; ji++) {
                asm("fma.rn.f32x2 %0, %1, %2, %0;"
                    : "+l"(acc[ri][ji]) : "l"(a[ri].x), "l"(w[ji].x));
                asm("fma.rn.f32x2 %0, %1, %2, %0;"
                    : "+l"(acc[ri][ji]) : "l"(a[ri].y), "l"(w[ji].y));
            }
    }
}

__global__ __launch_bounds__(256) void dual_linear_kernel(
        float* __restrict__ hid, float* __restrict__ out,
        const float* __restrict__ W, const float* __restrict__ b) {
    __shared__ __align__(16) float As[64 * SROW];
    __shared__ __align__(16) float Ws[64 * SROW];

    const int t = threadIdx.x;           // 256 threads
    const int row0 = blockIdx.x * 64;
    const int tx = t & 15;
    const int ty = t >> 4;

    // ---- phase 1: hid = A1 @ W^T + b ----
    #pragma unroll
    for (int i = t; i < 64 * 16; i += 256) {
        int j = i >> 4, k4 = i & 15;
        *reinterpret_cast<float4*>(&Ws[j * SROW + k4 * 4]) =
            reinterpret_cast<const float4*>(W)[j * 16 + k4];
    }
    stage_a_tile(As, g_a1, row0, t);
    __syncthreads();

    {
        unsigned long long acc[4][4];
        #pragma unroll
        for (int ri = 0; ri < 4; ri++)
            #pragma unroll
            for (int ji = 0; ji < 4; ji++) acc[ri][ji] = 0ull;
        gemm_tile(As, Ws, acc, tx, ty);
        float bj[4];
        #pragma unroll
        for (int ji = 0; ji < 4; ji++) bj[ji] = __ldg(&b[tx + 16 * ji]);
        #pragma unroll
        for (int ri = 0; ri < 4; ri++) {
            int row = row0 + ty * 4 + ri;
            if (row < N_NODES) {
                #pragma unroll
                for (int ji = 0; ji < 4; ji++) {
                    float lo, hi;
                    asm("mov.b64 {%0, %1}, %2;" : "=f"(lo), "=f"(hi) : "l"(acc[ri][ji]));
                    hid[(size_t)row * D + tx + 16 * ji] = lo + hi + bj[ji];
                }
            }
        }
    }
    __syncthreads();

    // ---- phase 2: out = A2 @ W2^T + deg*bW + b ----
    #pragma unroll
    for (int i = t; i < 64 * 16; i += 256) {
        int j = i >> 4, k4 = i & 15;
        *reinterpret_cast<float4*>(&Ws[j * SROW + k4 * 4]) =
            reinterpret_cast<const float4*>(g_W2)[j * 16 + k4];
    }
    stage_a_tile(As, g_a2, row0, t);
    __syncthreads();

    {
        unsigned long long acc[4][4];
        #pragma unroll
        for (int ri = 0; ri < 4; ri++)
            #pragma unroll
            for (int ji = 0; ji < 4; ji++) acc[ri][ji] = 0ull;
        gemm_tile(As, Ws, acc, tx, ty);
        float bj[4], bWj[4];
        #pragma unroll
        for (int ji = 0; ji < 4; ji++) {
            bj[ji]  = __ldg(&b[tx + 16 * ji]);
            bWj[ji] = __ldg(&g_bW[tx + 16 * ji]);
        }
        #pragma unroll
        for (int ri = 0; ri < 4; ri++) {
            int row = row0 + ty * 4 + ri;
            if (row < N_NODES) {
                float degf = __int2float_rn(__ldg(&g_cnt[row]));
                #pragma unroll
                for (int ji = 0; ji < 4; ji++) {
                    float lo, hi;
                    asm("mov.b64 {%0, %1}, %2;" : "=f"(lo), "=f"(hi) : "l"(acc[ri][ji]));
                    out[(size_t)row * D + tx + 16 * ji] = lo + hi + degf * bWj[ji] + bj[ji];
                }
            }
        }
    }
}

// ---------------------------------------------------------------------------
extern "C" void kernel_launch(void* const* d_in, const int* in_sizes, int n_in,
                              void* d_out, int out_size) {
    const float* x  = (const float*)d_in[0];
    const void*  ei = d_in[1];
    const float* W1 = (const float*)d_in[2];
    const float* b1 = (const float*)d_in[3];

    float* out = (float*)d_out;                      // (out, hid) flattened
    float* hid = out + (size_t)N_NODES * D;

    const int E8BLK = (N_EDGES / 8 + 255) / 256;     // 611
    const int GBLK  = (N_NODES * 32 + 255) / 256;    // 12500
    const int FBLK  = (N_NODES + 63) / 64;           // 1563

    init2_kernel<<<ZBLKS + 17, 256>>>((const unsigned*)ei, W1, b1);
    bucket_kernel<<<E8BLK, 256>>>(ei);
    gather_kernel<<<GBLK, 256>>>(x, 0);              // A1 = agg(x)
    gather_kernel<<<GBLK, 256>>>(x, 1);              // A2 = agg(A1)
    dual_linear_kernel<<<FBLK, 256>>>(hid, out, W1, b1);
}

// round 16
// speedup vs baseline: 1.0777x; 1.0777x over previous
#include <cuda_runtime.h>
#include <cstdint>

#define N_NODES 100000
#define N_EDGES 1250000
#define D 64
#define CAP 96                            // bucket capacity; P(deg>96)~1e-50; int4-aligned

// Scratch (static device globals — zero-initialized at load; g_cnt is
// re-zeroed by dual_linear_kernel at the end of every call, so each graph
// replay sees cnt == 0 without a dedicated zeroing pass).
__device__ __align__(128) float g_a1[(size_t)N_NODES * D];  // A1 = agg(x)
__device__ __align__(128) float g_a2[(size_t)N_NODES * D];  // A2 = agg(A1)
__device__ __align__(16) int g_slot[(size_t)N_NODES * CAP]; // bucketed src ids
__device__ int   g_cnt[((N_NODES + 63) / 64) * 64];         // degree / cursor (padded)
__device__ float g_W2[D * D];                  // W @ W
__device__ float g_bW[D];                      // b @ W^T
__device__ int   g_is64;

// ---------------------------------------------------------------------------
// prep: blocks [0,16) compute W2 = W@W; block 16: bW = b@W^T + i64 detect.
// ---------------------------------------------------------------------------
__global__ void prep_kernel(const unsigned* __restrict__ ei,
                            const float* __restrict__ W,
                            const float* __restrict__ b) {
    int t = threadIdx.x;                 // 256
    int bid = blockIdx.x;
    __shared__ float Wsh[D * D];
    #pragma unroll
    for (int i = t; i < D * D; i += 256) Wsh[i] = W[i];
    __syncthreads();
    if (bid < 16) {
        int o = bid * 256 + t;
        int j = o >> 6, k = o & 63;
        float s = 0.f;
        #pragma unroll
        for (int m = 0; m < D; m++) s += Wsh[j * D + m] * Wsh[m * D + k];
        g_W2[o] = s;
    } else {
        if (t < D) {
            float s = 0.f;
            #pragma unroll
            for (int k = 0; k < D; k++) s += b[k] * Wsh[t * D + k];
            g_bW[t] = s;
        } else if (t == 64) {
            int all0 = 1;
            #pragma unroll 1
            for (int k = 0; k < 64; k++) {
                if (ei[2 * k + 1] != 0u) { all0 = 0; break; }
            }
            g_is64 = all0;
        }
    }
}

// ---------------------------------------------------------------------------
// One-pass bucket fill: slot[dst*CAP + pos] = src. 8 edges/thread.
// ---------------------------------------------------------------------------
__global__ void bucket_kernel(const void* __restrict__ ei) {
    int q = blockIdx.x * blockDim.x + threadIdx.x;
    int e = q * 8;
    if (e >= N_EDGES) return;
    int s[8], d[8];
    if (g_is64) {
        const longlong2* ps = reinterpret_cast<const longlong2*>((const long long*)ei + e);
        const longlong2* pd = reinterpret_cast<const longlong2*>((const long long*)ei + N_EDGES + e);
        #pragma unroll
        for (int i = 0; i < 4; i++) {
            longlong2 a = __ldg(ps + i);
            longlong2 u = __ldg(pd + i);
            s[2 * i] = (int)a.x; s[2 * i + 1] = (int)a.y;
            d[2 * i] = (int)u.x; d[2 * i + 1] = (int)u.y;
        }
    } else {
        const int4* ps = reinterpret_cast<const int4*>((const int*)ei + e);
        const int4* pd = reinterpret_cast<const int4*>((const int*)ei + N_EDGES + e);
        #pragma unroll
        for (int i = 0; i < 2; i++) {
            int4 a = __ldg(ps + i);
            int4 u = __ldg(pd + i);
            s[4 * i] = a.x; s[4 * i + 1] = a.y; s[4 * i + 2] = a.z; s[4 * i + 3] = a.w;
            d[4 * i] = u.x; d[4 * i + 1] = u.y; d[4 * i + 2] = u.z; d[4 * i + 3] = u.w;
        }
    }
    int p[8];
    #pragma unroll
    for (int i = 0; i < 8; i++) p[i] = atomicAdd(&g_cnt[d[i]], 1);
    #pragma unroll
    for (int i = 0; i < 8; i++)
        if (p[i] < CAP) g_slot[(size_t)d[i] * CAP + p[i]] = s[i];
}

// ---------------------------------------------------------------------------
// Gather (fp32): phase 0: x -> g_a1, phase 1: g_a1 -> g_a2.
// 16 lanes per node (one float4 each). Slot indices loaded 4-at-a-time via
// int4; 4 independent guarded row loads per group. (R13 form — proven best.)
// ---------------------------------------------------------------------------
__global__ void gather_kernel(const float* __restrict__ x, int phase) {
    int t = blockIdx.x * blockDim.x + threadIdx.x;
    int node = t >> 4;
    int c = t & 15;
    if (node >= N_NODES) return;

    const float* in = phase ? g_a1 : x;
    float* outp     = phase ? g_a2 : g_a1;

    int cnt = __ldg(&g_cnt[node]);
    if (cnt > CAP) cnt = CAP;
    const int4* slots4 = reinterpret_cast<const int4*>(g_slot + (size_t)node * CAP);
    const int ngroups = (cnt + 3) >> 2;

    float4 acc = make_float4(0.f, 0.f, 0.f, 0.f);
    #pragma unroll 2
    for (int q = 0; q < ngroups; q++) {
        int4 s = __ldg(&slots4[q]);
        int base = q * 4;
        if (base + 0 < cnt) {
            float4 v = *reinterpret_cast<const float4*>(in + (size_t)s.x * D + c * 4);
            acc.x += v.x; acc.y += v.y; acc.z += v.z; acc.w += v.w;
        }
        if (base + 1 < cnt) {
            float4 v = *reinterpret_cast<const float4*>(in + (size_t)s.y * D + c * 4);
            acc.x += v.x; acc.y += v.y; acc.z += v.z; acc.w += v.w;
        }
        if (base + 2 < cnt) {
            float4 v = *reinterpret_cast<const float4*>(in + (size_t)s.z * D + c * 4);
            acc.x += v.x; acc.y += v.y; acc.z += v.z; acc.w += v.w;
        }
        if (base + 3 < cnt) {
            float4 v = *reinterpret_cast<const float4*>(in + (size_t)s.w * D + c * 4);
            acc.x += v.x; acc.y += v.y; acc.z += v.z; acc.w += v.w;
        }
    }
    *reinterpret_cast<float4*>(outp + (size_t)node * D + c * 4) = acc;
}

// ---------------------------------------------------------------------------
// Dual GEMM per 64-row tile:
//   phase 1:  hid = A1 @ W^T  + b
//   phase 2:  out = A2 @ W2^T + deg*bW + b
// 4x4 register tile, fma.rn.f32x2 (FFMA2). Tail: re-zero this block's g_cnt
// rows so the next graph replay sees cnt == 0 (no dedicated zero pass).
// ---------------------------------------------------------------------------
#define SROW 68

__device__ __forceinline__ void stage_a_tile(float* As, const float* __restrict__ src,
                                             int row0, int t) {
    #pragma unroll
    for (int i = t; i < 64 * 16; i += 256) {
        int r = i >> 4, k4 = i & 15;
        int row = row0 + r;
        float4 v = make_float4(0.f, 0.f, 0.f, 0.f);
        if (row < N_NODES)
            v = reinterpret_cast<const float4*>(src)[(size_t)row * 16 + k4];
        *reinterpret_cast<float4*>(&As[r * SROW + k4 * 4]) = v;
    }
}

__device__ __forceinline__ void gemm_tile(const float* As, const float* Ws,
                                          unsigned long long acc[4][4],
                                          int tx, int ty) {
    #pragma unroll 4
    for (int k4 = 0; k4 < 16; k4++) {
        ulonglong2 a[4], w[4];
        #pragma unroll
        for (int ri = 0; ri < 4; ri++)
            a[ri] = *reinterpret_cast<const ulonglong2*>(&As[(ty * 4 + ri) * SROW + k4 * 4]);
        #pragma unroll
        for (int ji = 0; ji < 4; ji++)
            w[ji] = *reinterpret_cast<const ulonglong2*>(&Ws[(tx + 16 * ji) * SROW + k4 * 4]);
        #pragma unroll
        for (int ri = 0; ri < 4; ri++)
            #pragma unroll
            for (int ji = 0; ji < 4; ji++) {
                asm("fma.rn.f32x2 %0, %1, %2, %0;"
                    : "+l"(acc[ri][ji]) : "l"(a[ri].x), "l"(w[ji].x));
                asm("fma.rn.f32x2 %0, %1, %2, %0;"
                    : "+l"(acc[ri][ji]) : "l"(a[ri].y), "l"(w[ji].y));
            }
    }
}

__global__ __launch_bounds__(256) void dual_linear_kernel(
        float* __restrict__ hid, float* __restrict__ out,
        const float* __restrict__ W, const float* __restrict__ b) {
    __shared__ __align__(16) float As[64 * SROW];
    __shared__ __align__(16) float Ws[64 * SROW];

    const int t = threadIdx.x;           // 256 threads
    const int row0 = blockIdx.x * 64;
    const int tx = t & 15;
    const int ty = t >> 4;

    // ---- phase 1: hid = A1 @ W^T + b ----
    #pragma unroll
    for (int i = t; i < 64 * 16; i += 256) {
        int j = i >> 4, k4 = i & 15;
        *reinterpret_cast<float4*>(&Ws[j * SROW + k4 * 4]) =
            reinterpret_cast<const float4*>(W)[j * 16 + k4];
    }
    stage_a_tile(As, g_a1, row0, t);
    __syncthreads();

    {
        unsigned long long acc[4][4];
        #pragma unroll
        for (int ri = 0; ri < 4; ri++)
            #pragma unroll
            for (int ji = 0; ji < 4; ji++) acc[ri][ji] = 0ull;
        gemm_tile(As, Ws, acc, tx, ty);
        float bj[4];
        #pragma unroll
        for (int ji = 0; ji < 4; ji++) bj[ji] = __ldg(&b[tx + 16 * ji]);
        #pragma unroll
        for (int ri = 0; ri < 4; ri++) {
            int row = row0 + ty * 4 + ri;
            if (row < N_NODES) {
                #pragma unroll
                for (int ji = 0; ji < 4; ji++) {
                    float lo, hi;
                    asm("mov.b64 {%0, %1}, %2;" : "=f"(lo), "=f"(hi) : "l"(acc[ri][ji]));
                    hid[(size_t)row * D + tx + 16 * ji] = lo + hi + bj[ji];
                }
            }
        }
    }
    __syncthreads();

    // ---- phase 2: out = A2 @ W2^T + deg*bW + b ----
    #pragma unroll
    for (int i = t; i < 64 * 16; i += 256) {
        int j = i >> 4, k4 = i & 15;
        *reinterpret_cast<float4*>(&Ws[j * SROW + k4 * 4]) =
            reinterpret_cast<const float4*>(g_W2)[j * 16 + k4];
    }
    stage_a_tile(As, g_a2, row0, t);
    __syncthreads();

    {
        unsigned long long acc[4][4];
        #pragma unroll
        for (int ri = 0; ri < 4; ri++)
            #pragma unroll
            for (int ji = 0; ji < 4; ji++) acc[ri][ji] = 0ull;
        gemm_tile(As, Ws, acc, tx, ty);
        float bj[4], bWj[4];
        #pragma unroll
        for (int ji = 0; ji < 4; ji++) {
            bj[ji]  = __ldg(&b[tx + 16 * ji]);
            bWj[ji] = __ldg(&g_bW[tx + 16 * ji]);
        }
        #pragma unroll
        for (int ri = 0; ri < 4; ri++) {
            int row = row0 + ty * 4 + ri;
            if (row < N_NODES) {
                float degf = __int2float_rn(__ldg(&g_cnt[row]));
                #pragma unroll
                for (int ji = 0; ji < 4; ji++) {
                    float lo, hi;
                    asm("mov.b64 {%0, %1}, %2;" : "=f"(lo), "=f"(hi) : "l"(acc[ri][ji]));
                    out[(size_t)row * D + tx + 16 * ji] = lo + hi + degf * bWj[ji] + bj[ji];
                }
            }
        }
    }

    // ---- tail: re-zero this block's g_cnt rows for the next replay ----
    __syncthreads();                     // all cnt reads of this block done
    if (t < 16) {
        int i4 = row0 + t * 4;           // 16 threads x int4 = 64 rows
        if (i4 < N_NODES)                // g_cnt padded to 64-multiple
            *reinterpret_cast<int4*>(&g_cnt[i4]) = make_int4(0, 0, 0, 0);
    }
}

// ---------------------------------------------------------------------------
extern "C" void kernel_launch(void* const* d_in, const int* in_sizes, int n_in,
                              void* d_out, int out_size) {
    const float* x  = (const float*)d_in[0];
    const void*  ei = d_in[1];
    const float* W1 = (const float*)d_in[2];
    const float* b1 = (const float*)d_in[3];

    float* out = (float*)d_out;                      // (out, hid) flattened
    float* hid = out + (size_t)N_NODES * D;

    const int E8BLK = (N_EDGES / 8 + 255) / 256;     // 611
    const int GBLK  = (N_NODES * 16 + 255) / 256;    // 6250
    const int FBLK  = (N_NODES + 63) / 64;           // 1563

    prep_kernel<<<17, 256>>>((const unsigned*)ei, W1, b1);
    bucket_kernel<<<E8BLK, 256>>>(ei);
    gather_kernel<<<GBLK, 256>>>(x, 0);              // A1 = agg(x)
    gather_kernel<<<GBLK, 256>>>(x, 1);              // A2 = agg(A1)
    dual_linear_kernel<<<FBLK, 256>>>(hid, out, W1, b1);
}